// round 7
// baseline (speedup 1.0000x reference)
#include <cuda_runtime.h>
#include <cuda_bf16.h>
#include <math_constants.h>

#define ROW_D      32000
#define ROW_D4     (ROW_D / 4)
#define CAP        2048
#define NTHREADS   256
#define NWARPS     (NTHREADS / 32)
#define KSLOTS     (CAP / NTHREADS)   // 8
#define NITER      50
#define NEWTON_IT  8
#define FULLMASK   0xFFFFFFFFu

__device__ __forceinline__ float pfun(float z, float cexp, bool sq) {
    if (z <= 0.0f) return 0.0f;
    return sq ? z * z : powf(z, cexp);
}

__global__ __launch_bounds__(NTHREADS, 8)
void entmax_bisect_kernel(const float* __restrict__ x,
                          const float* __restrict__ alpha_p,
                          float* __restrict__ out)
{
    __shared__ float  s_val[CAP];
    __shared__ int    s_idx[CAP];
    __shared__ float2 s_red2[NWARPS];
    __shared__ float  s_redb[2][NWARPS];
    __shared__ int    s_cnt;
    __shared__ float  s_max;
    __shared__ float  s_tau;
    __shared__ float2 s_fin;   // (tau_eval, fsum)

    const int tid  = threadIdx.x;
    const int lane = tid & 31;
    const int warp = tid >> 5;

    const float alpha = *alpha_p;
    const float am1   = alpha - 1.0f;
    const float cexp  = 1.0f / am1;
    const bool  sq    = (cexp == 2.0f);

    const size_t row_off = (size_t)blockIdx.x * ROW_D;
    const float4* __restrict__ row4 = reinterpret_cast<const float4*>(x + row_off);
    float*        __restrict__ orow  = out + row_off;
    float4*       __restrict__ orow4 = reinterpret_cast<float4*>(orow);

    if (tid == 0) s_cnt = 0;

    // ---- Phase 1: row max only (read-only: fills L2 with input lines) ----
    float m = -CUDART_INF_F;
    for (int i = tid; i < ROW_D4; i += NTHREADS) {
        float4 v = row4[i];
        m = fmaxf(m, fmaxf(fmaxf(v.x, v.y), fmaxf(v.z, v.w)));
    }
    #pragma unroll
    for (int o = 16; o; o >>= 1) m = fmaxf(m, __shfl_xor_sync(FULLMASK, m, o));
    if (lane == 0) s_redb[0][warp] = m;
    __syncthreads();
    if (warp == 0) {
        float mm = (lane < NWARPS) ? s_redb[0][lane] : -CUDART_INF_F;
        #pragma unroll
        for (int o = 16; o; o >>= 1) mm = fmaxf(mm, __shfl_xor_sync(FULLMASK, mm, o));
        if (lane == 0) s_max = mm * am1;
    }
    __syncthreads();

    const float Xmax   = s_max;
    const float tau_lo = Xmax - 1.0f;                 // candidates: X > tau_lo
    const float thr_x  = tau_lo / am1;                // same test in raw-x space (am1 > 0)
    const float tau_hi = Xmax - powf(1.0f / (float)ROW_D, am1);

    // ---- Phase 2: last-use re-read (evict-first) + zero-fill + compact ----
    for (int i = tid; i < ROW_D4; i += NTHREADS) {
        float4 v = __ldcs(&row4[i]);      // L2 hit expected; evict after use
        float vm = fmaxf(fmaxf(v.x, v.y), fmaxf(v.z, v.w));
        __stcs(&orow4[i], make_float4(0.f, 0.f, 0.f, 0.f));
        if (vm > thr_x) {                 // ~7.5% of quads
            if (v.x > thr_x) { int p = atomicAdd(&s_cnt, 1); if (p < CAP) { s_val[p] = v.x * am1; s_idx[p] = i * 4 + 0; } }
            if (v.y > thr_x) { int p = atomicAdd(&s_cnt, 1); if (p < CAP) { s_val[p] = v.y * am1; s_idx[p] = i * 4 + 1; } }
            if (v.z > thr_x) { int p = atomicAdd(&s_cnt, 1); if (p < CAP) { s_val[p] = v.z * am1; s_idx[p] = i * 4 + 2; } }
            if (v.w > thr_x) { int p = atomicAdd(&s_cnt, 1); if (p < CAP) { s_val[p] = v.w * am1; s_idx[p] = i * 4 + 3; } }
        }
    }
    __syncthreads();
    const int cnt = s_cnt;

    if (cnt <= CAP) {
        // pad candidate array to a multiple of NTHREADS with -INF (contributes 0)
        const int kmax = (cnt + NTHREADS - 1) / NTHREADS;   // uniform across block
        for (int j = cnt + tid; j < kmax * NTHREADS; j += NTHREADS)
            s_val[j] = -CUDART_INF_F;
        if (tid == 0) s_tau = tau_lo + 0.5f * (tau_hi - tau_lo);
        __syncthreads();

        if (sq) {
            // ---- Phase 3a: safeguarded Newton on f(t)=sum (X-t)_+^2 - 1 (convex, dec.) ----
            float lo = tau_lo, hi = tau_hi;   // meaningful only in warp0 lane0
            for (int it = 0; it < NEWTON_IT; ++it) {
                const float tau = s_tau;
                float f_loc = 0.0f, g_loc = 0.0f;
                #pragma unroll
                for (int k = 0; k < KSLOTS; ++k) {
                    if (k < kmax) {
                        float zp = fmaxf(s_val[tid + k * NTHREADS] - tau, 0.0f);
                        f_loc = fmaf(zp, zp, f_loc);
                        g_loc += zp;
                    }
                }
                #pragma unroll
                for (int o = 16; o; o >>= 1) {
                    f_loc += __shfl_xor_sync(FULLMASK, f_loc, o);
                    g_loc += __shfl_xor_sync(FULLMASK, g_loc, o);
                }
                if (lane == 0) s_red2[warp] = make_float2(f_loc, g_loc);
                __syncthreads();
                if (warp == 0) {
                    float2 p2 = (lane < NWARPS) ? s_red2[lane] : make_float2(0.f, 0.f);
                    float F = p2.x, G = p2.y;
                    #pragma unroll
                    for (int o = 4; o; o >>= 1) {
                        F += __shfl_xor_sync(FULLMASK, F, o);
                        G += __shfl_xor_sync(FULLMASK, G, o);
                    }
                    if (lane == 0) {
                        float f = F - 1.0f;
                        if (f >= 0.0f) lo = tau; else hi = tau;
                        float tn = tau + f / (2.0f * G);
                        if (!(tn >= lo && tn <= hi)) tn = 0.5f * (lo + hi);
                        s_tau = tn;
                        if (it == NEWTON_IT - 1) s_fin = make_float2(tau, F);
                    }
                }
                __syncthreads();
            }
            const float tauf = s_fin.x;
            const float invS = 1.0f / s_fin.y;
            for (int j = tid; j < cnt; j += NTHREADS) {
                float zp = fmaxf(s_val[j] - tauf, 0.0f);
                __stcs(&orow[s_idx[j]], zp * zp * invS);
            }
        } else {
            // ---- Phase 3a': general alpha — exact 50-iter bisection ----
            float f_lo_s = 0.0f;   // meaningful in warp0 lane0
            float dm = 0.0f, tlo = tau_lo;
            {
                float acc = 0.0f;
                #pragma unroll
                for (int k = 0; k < KSLOTS; ++k)
                    if (k < kmax) acc += pfun(s_val[tid + k * NTHREADS] - tau_lo, cexp, sq);
                #pragma unroll
                for (int o = 16; o; o >>= 1) acc += __shfl_xor_sync(FULLMASK, acc, o);
                if (lane == 0) s_red2[warp] = make_float2(acc, 0.f);
                __syncthreads();
                if (warp == 0) {
                    float F = (lane < NWARPS) ? s_red2[lane].x : 0.0f;
                    #pragma unroll
                    for (int o = 4; o; o >>= 1) F += __shfl_xor_sync(FULLMASK, F, o);
                    if (lane == 0) {
                        f_lo_s = F - 1.0f;
                        dm  = tau_hi - tau_lo;
                        s_tau = tau_lo + 0.5f * dm;
                    }
                }
                __syncthreads();
            }
            for (int it = 0; it < NITER; ++it) {
                const float tau = s_tau;
                float acc = 0.0f;
                #pragma unroll
                for (int k = 0; k < KSLOTS; ++k)
                    if (k < kmax) acc += pfun(s_val[tid + k * NTHREADS] - tau, cexp, sq);
                #pragma unroll
                for (int o = 16; o; o >>= 1) acc += __shfl_xor_sync(FULLMASK, acc, o);
                if (lane == 0) s_red2[warp] = make_float2(acc, 0.f);
                __syncthreads();
                if (warp == 0) {
                    float F = (lane < NWARPS) ? s_red2[lane].x : 0.0f;
                    #pragma unroll
                    for (int o = 4; o; o >>= 1) F += __shfl_xor_sync(FULLMASK, F, o);
                    if (lane == 0) {
                        if ((F - 1.0f) * f_lo_s >= 0.0f) tlo = tau;
                        dm *= 0.5f;
                        if (it == NITER - 1) s_fin = make_float2(tau, F);
                        else s_tau = tlo + 0.5f * dm;
                    }
                }
                __syncthreads();
            }
            const float tauf = s_fin.x;
            const float invS = 1.0f / s_fin.y;
            for (int j = tid; j < cnt; j += NTHREADS)
                __stcs(&orow[s_idx[j]], pfun(s_val[j] - tauf, cexp, sq) * invS);
        }
    } else {
        // ---- Fallback: full-row block-wide bisection (cnt > CAP; never expected) ----
        float acc = 0.0f;
        for (int j = tid; j < ROW_D; j += NTHREADS)
            acc += pfun(x[row_off + j] * am1 - tau_lo, cexp, sq);
        #pragma unroll
        for (int o = 16; o; o >>= 1) acc += __shfl_xor_sync(FULLMASK, acc, o);
        if (lane == 0) s_redb[1][warp] = acc;
        __syncthreads();
        float f_lo = -1.0f;
        #pragma unroll
        for (int w = 0; w < NWARPS; ++w) f_lo += s_redb[1][w];

        float dm = tau_hi - tau_lo;
        float tlo = tau_lo, tau_m = tau_lo, fsum = 1.0f;

        for (int it = 0; it < NITER; ++it) {
            dm *= 0.5f;
            tau_m = tlo + dm;
            acc = 0.0f;
            for (int j = tid; j < ROW_D; j += NTHREADS)
                acc += pfun(x[row_off + j] * am1 - tau_m, cexp, sq);
            #pragma unroll
            for (int o = 16; o; o >>= 1) acc += __shfl_xor_sync(FULLMASK, acc, o);
            const int buf = it & 1;
            if (lane == 0) s_redb[buf][warp] = acc;
            __syncthreads();
            fsum = 0.0f;
            #pragma unroll
            for (int w = 0; w < NWARPS; ++w) fsum += s_redb[buf][w];
            if ((fsum - 1.0f) * f_lo >= 0.0f) tlo = tau_m;
        }

        const float invS = 1.0f / fsum;
        for (int i = tid; i < ROW_D4; i += NTHREADS) {
            float4 v = row4[i];
            float4 r;
            r.x = pfun(v.x * am1 - tau_m, cexp, sq) * invS;
            r.y = pfun(v.y * am1 - tau_m, cexp, sq) * invS;
            r.z = pfun(v.z * am1 - tau_m, cexp, sq) * invS;
            r.w = pfun(v.w * am1 - tau_m, cexp, sq) * invS;
            __stcs(&orow4[i], r);
        }
    }
}

extern "C" void kernel_launch(void* const* d_in, const int* in_sizes, int n_in,
                              void* d_out, int out_size)
{
    const float* x     = (const float*)d_in[0];
    const float* alpha = (const float*)d_in[1];
    float*       out   = (float*)d_out;

    const int rows = in_sizes[0] / ROW_D;
    entmax_bisect_kernel<<<rows, NTHREADS>>>(x, alpha, out);
}

// round 8
// speedup vs baseline: 1.4793x; 1.4793x over previous
#include <cuda_runtime.h>
#include <cuda_bf16.h>
#include <math_constants.h>

#define ROW_D      32000
#define ROW_D4     (ROW_D / 4)          // 8000 quads
#define CAP        3072
#define NTHREADS   512
#define NWARPS     (NTHREADS / 32)
#define KSLOTS     (CAP / NTHREADS)     // 6
#define SAMPLE_Q   2048                 // sampled quads (8192 elements, 32 KB)
#define GROUP      (NTHREADS * 4)       // 2048 quads per outer iter
#define NFULL      3                    // 3 * 2048 = 6144 unconditional quads
#define TAIL_BASE  (NFULL * GROUP)      // 6144
#define NITER      50
#define NEWTON_IT  8
#define FULLMASK   0xFFFFFFFFu

__device__ __forceinline__ float pfun(float z, float cexp, bool sq) {
    if (z <= 0.0f) return 0.0f;
    return sq ? z * z : powf(z, cexp);
}

__device__ __forceinline__ float max4(float4 v) {
    return fmaxf(fmaxf(v.x, v.y), fmaxf(v.z, v.w));
}

__global__ __launch_bounds__(NTHREADS, 4)
void entmax_bisect_kernel(const float* __restrict__ x,
                          const float* __restrict__ alpha_p,
                          float* __restrict__ out)
{
    __shared__ float  s_val[CAP];
    __shared__ int    s_idx[CAP];
    __shared__ float2 s_red2[NWARPS];
    __shared__ float  s_redb[2][NWARPS];
    __shared__ int    s_cnt;
    __shared__ float  s_bcast;
    __shared__ float  s_tau;
    __shared__ float2 s_fin;   // (tau_eval, fsum)

    const int tid  = threadIdx.x;
    const int lane = tid & 31;
    const int warp = tid >> 5;

    const float alpha = *alpha_p;
    const float am1   = alpha - 1.0f;
    const float cexp  = 1.0f / am1;
    const bool  sq    = (cexp == 2.0f);

    const size_t row_off = (size_t)blockIdx.x * ROW_D;
    const float4* __restrict__ row4 = reinterpret_cast<const float4*>(x + row_off);
    float*        __restrict__ orow  = out + row_off;
    float4*       __restrict__ orow4 = reinterpret_cast<float4*>(orow);

    if (tid == 0) s_cnt = 0;

    // ---- Phase 0: sampled max over first SAMPLE_Q quads (32 KB, coalesced) ----
    float ms = -CUDART_INF_F;
    #pragma unroll
    for (int k = 0; k < SAMPLE_Q / NTHREADS; ++k) {
        float4 v = row4[tid + k * NTHREADS];
        ms = fmaxf(ms, max4(v));
    }
    #pragma unroll
    for (int o = 16; o; o >>= 1) ms = fmaxf(ms, __shfl_xor_sync(FULLMASK, ms, o));
    if (lane == 0) s_redb[0][warp] = ms;
    __syncthreads();
    if (warp == 0) {
        float mm = (lane < NWARPS) ? s_redb[0][lane] : -CUDART_INF_F;
        #pragma unroll
        for (int o = 16; o; o >>= 1) mm = fmaxf(mm, __shfl_xor_sync(FULLMASK, mm, o));
        if (lane == 0) s_bcast = mm;
    }
    __syncthreads();
    // conservative raw-x threshold: sample max <= true max, so collection is a
    // superset of {X > Xmax - 1}; extras contribute exactly 0 for tau >= tau_lo.
    const float thr = s_bcast - cexp;    // x-space: xmax_s - 1/am1

    // ---- Phase 1 (single full pass, software-pipelined by 4):
    //      true max + zero-fill + conservative collect ----
    float m = -CUDART_INF_F;
    const float4 ZQ = make_float4(0.f, 0.f, 0.f, 0.f);

    #pragma unroll
    for (int ot = 0; ot < NFULL; ++ot) {
        const int base = ot * GROUP + tid;
        float4 v0 = row4[base];
        float4 v1 = row4[base +     NTHREADS];
        float4 v2 = row4[base + 2 * NTHREADS];
        float4 v3 = row4[base + 3 * NTHREADS];
        __stcs(&orow4[base],                ZQ);
        __stcs(&orow4[base +     NTHREADS], ZQ);
        __stcs(&orow4[base + 2 * NTHREADS], ZQ);
        __stcs(&orow4[base + 3 * NTHREADS], ZQ);
        float m0 = max4(v0), m1 = max4(v1), m2 = max4(v2), m3 = max4(v3);
        m = fmaxf(m, fmaxf(fmaxf(m0, m1), fmaxf(m2, m3)));
        if (fmaxf(fmaxf(m0, m1), fmaxf(m2, m3)) > thr) {   // rare
            const float4  vv[4] = { v0, v1, v2, v3 };
            #pragma unroll
            for (int k = 0; k < 4; ++k) {
                const int idx = (base + k * NTHREADS) * 4;
                const float4 v = vv[k];
                if (v.x > thr) { int p = atomicAdd(&s_cnt, 1); if (p < CAP) { s_val[p] = v.x * am1; s_idx[p] = idx + 0; } }
                if (v.y > thr) { int p = atomicAdd(&s_cnt, 1); if (p < CAP) { s_val[p] = v.y * am1; s_idx[p] = idx + 1; } }
                if (v.z > thr) { int p = atomicAdd(&s_cnt, 1); if (p < CAP) { s_val[p] = v.z * am1; s_idx[p] = idx + 2; } }
                if (v.w > thr) { int p = atomicAdd(&s_cnt, 1); if (p < CAP) { s_val[p] = v.w * am1; s_idx[p] = idx + 3; } }
            }
        }
    }
    // tail: quads [6144, 8000)
    {
        const int base = TAIL_BASE + tid;
        float4 v0, v1, v2, v3;
        const bool b0 = (base                 < ROW_D4);
        const bool b1 = (base +     NTHREADS  < ROW_D4);
        const bool b2 = (base + 2 * NTHREADS  < ROW_D4);
        const bool b3 = (base + 3 * NTHREADS  < ROW_D4);
        if (b0) v0 = row4[base];
        if (b1) v1 = row4[base +     NTHREADS];
        if (b2) v2 = row4[base + 2 * NTHREADS];
        if (b3) v3 = row4[base + 3 * NTHREADS];
        if (b0) __stcs(&orow4[base],                ZQ);
        if (b1) __stcs(&orow4[base +     NTHREADS], ZQ);
        if (b2) __stcs(&orow4[base + 2 * NTHREADS], ZQ);
        if (b3) __stcs(&orow4[base + 3 * NTHREADS], ZQ);
        float mx = -CUDART_INF_F;
        if (b0) mx = fmaxf(mx, max4(v0));
        if (b1) mx = fmaxf(mx, max4(v1));
        if (b2) mx = fmaxf(mx, max4(v2));
        if (b3) mx = fmaxf(mx, max4(v3));
        m = fmaxf(m, mx);
        if (mx > thr) {
            #pragma unroll
            for (int k = 0; k < 4; ++k) {
                const int qi = base + k * NTHREADS;
                if (qi < ROW_D4) {
                    const float4 v = (k == 0) ? v0 : (k == 1) ? v1 : (k == 2) ? v2 : v3;
                    const int idx = qi * 4;
                    if (v.x > thr) { int p = atomicAdd(&s_cnt, 1); if (p < CAP) { s_val[p] = v.x * am1; s_idx[p] = idx + 0; } }
                    if (v.y > thr) { int p = atomicAdd(&s_cnt, 1); if (p < CAP) { s_val[p] = v.y * am1; s_idx[p] = idx + 1; } }
                    if (v.z > thr) { int p = atomicAdd(&s_cnt, 1); if (p < CAP) { s_val[p] = v.z * am1; s_idx[p] = idx + 2; } }
                    if (v.w > thr) { int p = atomicAdd(&s_cnt, 1); if (p < CAP) { s_val[p] = v.w * am1; s_idx[p] = idx + 3; } }
                }
            }
        }
    }

    // true-max reduce
    #pragma unroll
    for (int o = 16; o; o >>= 1) m = fmaxf(m, __shfl_xor_sync(FULLMASK, m, o));
    if (lane == 0) s_redb[1][warp] = m;
    __syncthreads();
    if (warp == 0) {
        float mm = (lane < NWARPS) ? s_redb[1][lane] : -CUDART_INF_F;
        #pragma unroll
        for (int o = 16; o; o >>= 1) mm = fmaxf(mm, __shfl_xor_sync(FULLMASK, mm, o));
        if (lane == 0) s_bcast = mm * am1;   // exact Xmax
    }
    __syncthreads();

    const float Xmax   = s_bcast;
    const float tau_lo = Xmax - 1.0f;
    const float tau_hi = Xmax - powf(1.0f / (float)ROW_D, am1);
    const int   cnt    = s_cnt;

    if (cnt <= CAP) {
        const int kmax = (cnt + NTHREADS - 1) / NTHREADS;
        for (int j = cnt + tid; j < kmax * NTHREADS; j += NTHREADS)
            s_val[j] = -CUDART_INF_F;
        if (tid == 0) s_tau = tau_lo + 0.5f * (tau_hi - tau_lo);
        __syncthreads();

        if (sq) {
            // ---- safeguarded Newton on f(t)=sum (X-t)_+^2 - 1 (convex, decreasing) ----
            float lo = tau_lo, hi = tau_hi;   // warp0 lane0 state
            for (int it = 0; it < NEWTON_IT; ++it) {
                const float tau = s_tau;
                float f_loc = 0.0f, g_loc = 0.0f;
                #pragma unroll
                for (int k = 0; k < KSLOTS; ++k) {
                    if (k < kmax) {
                        float zp = fmaxf(s_val[tid + k * NTHREADS] - tau, 0.0f);
                        f_loc = fmaf(zp, zp, f_loc);
                        g_loc += zp;
                    }
                }
                #pragma unroll
                for (int o = 16; o; o >>= 1) {
                    f_loc += __shfl_xor_sync(FULLMASK, f_loc, o);
                    g_loc += __shfl_xor_sync(FULLMASK, g_loc, o);
                }
                if (lane == 0) s_red2[warp] = make_float2(f_loc, g_loc);
                __syncthreads();
                if (warp == 0) {
                    float2 p2 = (lane < NWARPS) ? s_red2[lane] : make_float2(0.f, 0.f);
                    float F = p2.x, G = p2.y;
                    #pragma unroll
                    for (int o = 8; o; o >>= 1) {
                        F += __shfl_xor_sync(FULLMASK, F, o);
                        G += __shfl_xor_sync(FULLMASK, G, o);
                    }
                    if (lane == 0) {
                        float f = F - 1.0f;
                        if (f >= 0.0f) lo = tau; else hi = tau;
                        float tn = tau + f / (2.0f * G);
                        if (!(tn >= lo && tn <= hi)) tn = 0.5f * (lo + hi);
                        s_tau = tn;
                        if (it == NEWTON_IT - 1) s_fin = make_float2(tau, F);
                    }
                }
                __syncthreads();
            }
            const float tauf = s_fin.x;
            const float invS = 1.0f / s_fin.y;
            for (int j = tid; j < cnt; j += NTHREADS) {
                float zp = fmaxf(s_val[j] - tauf, 0.0f);
                __stcs(&orow[s_idx[j]], zp * zp * invS);
            }
        } else {
            // ---- general alpha: exact 50-iter bisection ----
            float f_lo_s = 0.0f, dm = 0.0f, tlo = tau_lo;
            {
                float acc = 0.0f;
                #pragma unroll
                for (int k = 0; k < KSLOTS; ++k)
                    if (k < kmax) acc += pfun(s_val[tid + k * NTHREADS] - tau_lo, cexp, sq);
                #pragma unroll
                for (int o = 16; o; o >>= 1) acc += __shfl_xor_sync(FULLMASK, acc, o);
                if (lane == 0) s_red2[warp] = make_float2(acc, 0.f);
                __syncthreads();
                if (warp == 0) {
                    float F = (lane < NWARPS) ? s_red2[lane].x : 0.0f;
                    #pragma unroll
                    for (int o = 8; o; o >>= 1) F += __shfl_xor_sync(FULLMASK, F, o);
                    if (lane == 0) {
                        f_lo_s = F - 1.0f;
                        dm  = tau_hi - tau_lo;
                        s_tau = tau_lo + 0.5f * dm;
                    }
                }
                __syncthreads();
            }
            for (int it = 0; it < NITER; ++it) {
                const float tau = s_tau;
                float acc = 0.0f;
                #pragma unroll
                for (int k = 0; k < KSLOTS; ++k)
                    if (k < kmax) acc += pfun(s_val[tid + k * NTHREADS] - tau, cexp, sq);
                #pragma unroll
                for (int o = 16; o; o >>= 1) acc += __shfl_xor_sync(FULLMASK, acc, o);
                if (lane == 0) s_red2[warp] = make_float2(acc, 0.f);
                __syncthreads();
                if (warp == 0) {
                    float F = (lane < NWARPS) ? s_red2[lane].x : 0.0f;
                    #pragma unroll
                    for (int o = 8; o; o >>= 1) F += __shfl_xor_sync(FULLMASK, F, o);
                    if (lane == 0) {
                        if ((F - 1.0f) * f_lo_s >= 0.0f) tlo = tau;
                        dm *= 0.5f;
                        if (it == NITER - 1) s_fin = make_float2(tau, F);
                        else s_tau = tlo + 0.5f * dm;
                    }
                }
                __syncthreads();
            }
            const float tauf = s_fin.x;
            const float invS = 1.0f / s_fin.y;
            for (int j = tid; j < cnt; j += NTHREADS)
                __stcs(&orow[s_idx[j]], pfun(s_val[j] - tauf, cexp, sq) * invS);
        }
    } else {
        // ---- Fallback: full-row block-wide bisection (cnt > CAP; never expected) ----
        float acc = 0.0f;
        for (int j = tid; j < ROW_D; j += NTHREADS)
            acc += pfun(x[row_off + j] * am1 - tau_lo, cexp, sq);
        #pragma unroll
        for (int o = 16; o; o >>= 1) acc += __shfl_xor_sync(FULLMASK, acc, o);
        if (lane == 0) s_redb[1][warp] = acc;
        __syncthreads();
        float f_lo = -1.0f;
        #pragma unroll
        for (int w = 0; w < NWARPS; ++w) f_lo += s_redb[1][w];

        float dm = tau_hi - tau_lo;
        float tlo = tau_lo, tau_m = tau_lo, fsum = 1.0f;

        for (int it = 0; it < NITER; ++it) {
            dm *= 0.5f;
            tau_m = tlo + dm;
            acc = 0.0f;
            for (int j = tid; j < ROW_D; j += NTHREADS)
                acc += pfun(x[row_off + j] * am1 - tau_m, cexp, sq);
            #pragma unroll
            for (int o = 16; o; o >>= 1) acc += __shfl_xor_sync(FULLMASK, acc, o);
            const int buf = it & 1;
            if (lane == 0) s_redb[buf][warp] = acc;
            __syncthreads();
            fsum = 0.0f;
            #pragma unroll
            for (int w = 0; w < NWARPS; ++w) fsum += s_redb[buf][w];
            if ((fsum - 1.0f) * f_lo >= 0.0f) tlo = tau_m;
        }

        const float invS = 1.0f / fsum;
        for (int i = tid; i < ROW_D4; i += NTHREADS) {
            float4 v = row4[i];
            float4 r;
            r.x = pfun(v.x * am1 - tau_m, cexp, sq) * invS;
            r.y = pfun(v.y * am1 - tau_m, cexp, sq) * invS;
            r.z = pfun(v.z * am1 - tau_m, cexp, sq) * invS;
            r.w = pfun(v.w * am1 - tau_m, cexp, sq) * invS;
            __stcs(&orow4[i], r);
        }
    }
}

extern "C" void kernel_launch(void* const* d_in, const int* in_sizes, int n_in,
                              void* d_out, int out_size)
{
    const float* x     = (const float*)d_in[0];
    const float* alpha = (const float*)d_in[1];
    float*       out   = (float*)d_out;

    const int rows = in_sizes[0] / ROW_D;
    entmax_bisect_kernel<<<rows, NTHREADS>>>(x, alpha, out);
}

// round 9
// speedup vs baseline: 3.7639x; 2.5443x over previous
#include <cuda_runtime.h>
#include <cuda_bf16.h>
#include <math_constants.h>

#define ROW_D      32000
#define ROW_D4     (ROW_D / 4)          // 8000 quads
#define CAP        3072
#define NTHREADS   512
#define NWARPS     (NTHREADS / 32)
#define KSLOTS     (CAP / NTHREADS)     // 6
#define NITER      50
#define NEWTON_IT  8
#define FULLMASK   0xFFFFFFFFu
// row tiling: 2 full groups of 6*512=3072 quads, then 3*512 + 320 tail
#define G_FULL     3072
#define TAIL0      6144                 // quads [6144, 7680): 3 unconditional slots
#define TAIL1      7680                 // quads [7680, 8000): tid < 320

__device__ __forceinline__ float pfun(float z, float cexp, bool sq) {
    if (z <= 0.0f) return 0.0f;
    return sq ? z * z : powf(z, cexp);
}

__device__ __forceinline__ float max4(float4 v) {
    return fmaxf(fmaxf(v.x, v.y), fmaxf(v.z, v.w));
}

__global__ __launch_bounds__(NTHREADS, 3)
void entmax_bisect_kernel(const float* __restrict__ x,
                          const float* __restrict__ alpha_p,
                          float* __restrict__ out)
{
    __shared__ float  s_val[CAP];
    __shared__ int    s_idx[CAP];
    __shared__ float2 s_red2[NWARPS];
    __shared__ float  s_redb[2][NWARPS];
    __shared__ int    s_cnt;
    __shared__ float  s_max;
    __shared__ float  s_tau;
    __shared__ float2 s_fin;   // (tau_eval, fsum)

    const int tid  = threadIdx.x;
    const int lane = tid & 31;
    const int warp = tid >> 5;

    const float alpha = *alpha_p;
    const float am1   = alpha - 1.0f;
    const float cexp  = 1.0f / am1;
    const bool  sq    = (cexp == 2.0f);

    const size_t row_off = (size_t)blockIdx.x * ROW_D;
    const float4* __restrict__ row4 = reinterpret_cast<const float4*>(x + row_off);
    float*        __restrict__ orow  = out + row_off;
    float4*       __restrict__ orow4 = reinterpret_cast<float4*>(orow);

    if (tid == 0) s_cnt = 0;

    // ---- Phase 1: row max, read-only, 6 loads in flight per thread ----
    float m = -CUDART_INF_F;
    #pragma unroll
    for (int g = 0; g < 2; ++g) {
        const int base = g * G_FULL + tid;
        float4 v0 = row4[base];
        float4 v1 = row4[base +     NTHREADS];
        float4 v2 = row4[base + 2 * NTHREADS];
        float4 v3 = row4[base + 3 * NTHREADS];
        float4 v4 = row4[base + 4 * NTHREADS];
        float4 v5 = row4[base + 5 * NTHREADS];
        float a = fmaxf(max4(v0), max4(v1));
        float b = fmaxf(max4(v2), max4(v3));
        float c = fmaxf(max4(v4), max4(v5));
        m = fmaxf(m, fmaxf(a, fmaxf(b, c)));
    }
    {
        const int base = TAIL0 + tid;
        float4 v0 = row4[base];
        float4 v1 = row4[base +     NTHREADS];
        float4 v2 = row4[base + 2 * NTHREADS];
        float t = fmaxf(max4(v0), fmaxf(max4(v1), max4(v2)));
        if (tid < (ROW_D4 - TAIL1)) t = fmaxf(t, max4(row4[TAIL1 + tid]));
        m = fmaxf(m, t);
    }
    #pragma unroll
    for (int o = 16; o; o >>= 1) m = fmaxf(m, __shfl_xor_sync(FULLMASK, m, o));
    if (lane == 0) s_redb[0][warp] = m;
    __syncthreads();
    if (warp == 0) {
        float mm = (lane < NWARPS) ? s_redb[0][lane] : -CUDART_INF_F;
        #pragma unroll
        for (int o = 16; o; o >>= 1) mm = fmaxf(mm, __shfl_xor_sync(FULLMASK, mm, o));
        if (lane == 0) s_max = mm * am1;
    }
    __syncthreads();

    const float Xmax   = s_max;
    const float tau_lo = Xmax - 1.0f;                 // candidates: X > tau_lo
    const float thr_x  = tau_lo / am1;                // same test in raw-x space (am1 > 0)
    const float tau_hi = Xmax - powf(1.0f / (float)ROW_D, am1);
    const float4 ZQ = make_float4(0.f, 0.f, 0.f, 0.f);

    // ---- Phase 2: L2 re-read (evict-first), zero-fill, compact — 6-deep batches ----
    #pragma unroll
    for (int g = 0; g < 2; ++g) {
        const int base = g * G_FULL + tid;
        float4 v[6];
        #pragma unroll
        for (int k = 0; k < 6; ++k) v[k] = __ldcs(&row4[base + k * NTHREADS]);
        #pragma unroll
        for (int k = 0; k < 6; ++k) __stcs(&orow4[base + k * NTHREADS], ZQ);
        #pragma unroll
        for (int k = 0; k < 6; ++k) {
            if (max4(v[k]) > thr_x) {      // rare
                const int idx = (base + k * NTHREADS) * 4;
                const float4 q = v[k];
                if (q.x > thr_x) { int p = atomicAdd(&s_cnt, 1); if (p < CAP) { s_val[p] = q.x * am1; s_idx[p] = idx + 0; } }
                if (q.y > thr_x) { int p = atomicAdd(&s_cnt, 1); if (p < CAP) { s_val[p] = q.y * am1; s_idx[p] = idx + 1; } }
                if (q.z > thr_x) { int p = atomicAdd(&s_cnt, 1); if (p < CAP) { s_val[p] = q.z * am1; s_idx[p] = idx + 2; } }
                if (q.w > thr_x) { int p = atomicAdd(&s_cnt, 1); if (p < CAP) { s_val[p] = q.w * am1; s_idx[p] = idx + 3; } }
            }
        }
    }
    {
        const int base = TAIL0 + tid;
        const bool bt = tid < (ROW_D4 - TAIL1);
        float4 v[4];
        #pragma unroll
        for (int k = 0; k < 3; ++k) v[k] = __ldcs(&row4[base + k * NTHREADS]);
        if (bt) v[3] = __ldcs(&row4[TAIL1 + tid]);
        #pragma unroll
        for (int k = 0; k < 3; ++k) __stcs(&orow4[base + k * NTHREADS], ZQ);
        if (bt) __stcs(&orow4[TAIL1 + tid], ZQ);
        #pragma unroll
        for (int k = 0; k < 4; ++k) {
            const bool ok = (k < 3) || bt;
            if (ok && max4(v[k]) > thr_x) {
                const int idx = ((k < 3) ? (base + k * NTHREADS) : (TAIL1 + tid)) * 4;
                const float4 q = v[k];
                if (q.x > thr_x) { int p = atomicAdd(&s_cnt, 1); if (p < CAP) { s_val[p] = q.x * am1; s_idx[p] = idx + 0; } }
                if (q.y > thr_x) { int p = atomicAdd(&s_cnt, 1); if (p < CAP) { s_val[p] = q.y * am1; s_idx[p] = idx + 1; } }
                if (q.z > thr_x) { int p = atomicAdd(&s_cnt, 1); if (p < CAP) { s_val[p] = q.z * am1; s_idx[p] = idx + 2; } }
                if (q.w > thr_x) { int p = atomicAdd(&s_cnt, 1); if (p < CAP) { s_val[p] = q.w * am1; s_idx[p] = idx + 3; } }
            }
        }
    }
    __syncthreads();
    const int cnt = s_cnt;

    if (cnt <= CAP) {
        const int kmax = (cnt + NTHREADS - 1) / NTHREADS;   // uniform across block
        for (int j = cnt + tid; j < kmax * NTHREADS; j += NTHREADS)
            s_val[j] = -CUDART_INF_F;
        if (tid == 0) s_tau = tau_lo + 0.5f * (tau_hi - tau_lo);
        __syncthreads();

        if (sq) {
            // ---- safeguarded Newton on f(t)=sum (X-t)_+^2 - 1 (convex, decreasing) ----
            float lo = tau_lo, hi = tau_hi;   // warp0 lane0 state
            for (int it = 0; it < NEWTON_IT; ++it) {
                const float tau = s_tau;
                float f_loc = 0.0f, g_loc = 0.0f;
                #pragma unroll
                for (int k = 0; k < KSLOTS; ++k) {
                    if (k < kmax) {
                        float zp = fmaxf(s_val[tid + k * NTHREADS] - tau, 0.0f);
                        f_loc = fmaf(zp, zp, f_loc);
                        g_loc += zp;
                    }
                }
                #pragma unroll
                for (int o = 16; o; o >>= 1) {
                    f_loc += __shfl_xor_sync(FULLMASK, f_loc, o);
                    g_loc += __shfl_xor_sync(FULLMASK, g_loc, o);
                }
                if (lane == 0) s_red2[warp] = make_float2(f_loc, g_loc);
                __syncthreads();
                if (warp == 0) {
                    float2 p2 = (lane < NWARPS) ? s_red2[lane] : make_float2(0.f, 0.f);
                    float F = p2.x, G = p2.y;
                    #pragma unroll
                    for (int o = 8; o; o >>= 1) {
                        F += __shfl_xor_sync(FULLMASK, F, o);
                        G += __shfl_xor_sync(FULLMASK, G, o);
                    }
                    if (lane == 0) {
                        float f = F - 1.0f;
                        if (f >= 0.0f) lo = tau; else hi = tau;
                        float tn = tau + f / (2.0f * G);
                        if (!(tn >= lo && tn <= hi)) tn = 0.5f * (lo + hi);
                        s_tau = tn;
                        if (it == NEWTON_IT - 1) s_fin = make_float2(tau, F);
                    }
                }
                __syncthreads();
            }
            const float tauf = s_fin.x;
            const float invS = 1.0f / s_fin.y;
            for (int j = tid; j < cnt; j += NTHREADS) {
                float zp = fmaxf(s_val[j] - tauf, 0.0f);
                __stcs(&orow[s_idx[j]], zp * zp * invS);
            }
        } else {
            // ---- general alpha: exact 50-iter bisection ----
            float f_lo_s = 0.0f, dm = 0.0f, tlo = tau_lo;
            {
                float acc = 0.0f;
                #pragma unroll
                for (int k = 0; k < KSLOTS; ++k)
                    if (k < kmax) acc += pfun(s_val[tid + k * NTHREADS] - tau_lo, cexp, sq);
                #pragma unroll
                for (int o = 16; o; o >>= 1) acc += __shfl_xor_sync(FULLMASK, acc, o);
                if (lane == 0) s_red2[warp] = make_float2(acc, 0.f);
                __syncthreads();
                if (warp == 0) {
                    float F = (lane < NWARPS) ? s_red2[lane].x : 0.0f;
                    #pragma unroll
                    for (int o = 8; o; o >>= 1) F += __shfl_xor_sync(FULLMASK, F, o);
                    if (lane == 0) {
                        f_lo_s = F - 1.0f;
                        dm  = tau_hi - tau_lo;
                        s_tau = tau_lo + 0.5f * dm;
                    }
                }
                __syncthreads();
            }
            for (int it = 0; it < NITER; ++it) {
                const float tau = s_tau;
                float acc = 0.0f;
                #pragma unroll
                for (int k = 0; k < KSLOTS; ++k)
                    if (k < kmax) acc += pfun(s_val[tid + k * NTHREADS] - tau, cexp, sq);
                #pragma unroll
                for (int o = 16; o; o >>= 1) acc += __shfl_xor_sync(FULLMASK, acc, o);
                if (lane == 0) s_red2[warp] = make_float2(acc, 0.f);
                __syncthreads();
                if (warp == 0) {
                    float F = (lane < NWARPS) ? s_red2[lane].x : 0.0f;
                    #pragma unroll
                    for (int o = 8; o; o >>= 1) F += __shfl_xor_sync(FULLMASK, F, o);
                    if (lane == 0) {
                        if ((F - 1.0f) * f_lo_s >= 0.0f) tlo = tau;
                        dm *= 0.5f;
                        if (it == NITER - 1) s_fin = make_float2(tau, F);
                        else s_tau = tlo + 0.5f * dm;
                    }
                }
                __syncthreads();
            }
            const float tauf = s_fin.x;
            const float invS = 1.0f / s_fin.y;
            for (int j = tid; j < cnt; j += NTHREADS)
                __stcs(&orow[s_idx[j]], pfun(s_val[j] - tauf, cexp, sq) * invS);
        }
    } else {
        // ---- Fallback: full-row block-wide bisection (cnt > CAP; never expected) ----
        float acc = 0.0f;
        for (int j = tid; j < ROW_D; j += NTHREADS)
            acc += pfun(x[row_off + j] * am1 - tau_lo, cexp, sq);
        #pragma unroll
        for (int o = 16; o; o >>= 1) acc += __shfl_xor_sync(FULLMASK, acc, o);
        if (lane == 0) s_redb[1][warp] = acc;
        __syncthreads();
        float f_lo = -1.0f;
        #pragma unroll
        for (int w = 0; w < NWARPS; ++w) f_lo += s_redb[1][w];

        float dm = tau_hi - tau_lo;
        float tlo = tau_lo, tau_m = tau_lo, fsum = 1.0f;

        for (int it = 0; it < NITER; ++it) {
            dm *= 0.5f;
            tau_m = tlo + dm;
            acc = 0.0f;
            for (int j = tid; j < ROW_D; j += NTHREADS)
                acc += pfun(x[row_off + j] * am1 - tau_m, cexp, sq);
            #pragma unroll
            for (int o = 16; o; o >>= 1) acc += __shfl_xor_sync(FULLMASK, acc, o);
            const int buf = it & 1;
            if (lane == 0) s_redb[buf][warp] = acc;
            __syncthreads();
            fsum = 0.0f;
            #pragma unroll
            for (int w = 0; w < NWARPS; ++w) fsum += s_redb[buf][w];
            if ((fsum - 1.0f) * f_lo >= 0.0f) tlo = tau_m;
        }

        const float invS = 1.0f / fsum;
        for (int i = tid; i < ROW_D4; i += NTHREADS) {
            float4 v = row4[i];
            float4 r;
            r.x = pfun(v.x * am1 - tau_m, cexp, sq) * invS;
            r.y = pfun(v.y * am1 - tau_m, cexp, sq) * invS;
            r.z = pfun(v.z * am1 - tau_m, cexp, sq) * invS;
            r.w = pfun(v.w * am1 - tau_m, cexp, sq) * invS;
            __stcs(&orow4[i], r);
        }
    }
}

extern "C" void kernel_launch(void* const* d_in, const int* in_sizes, int n_in,
                              void* d_out, int out_size)
{
    const float* x     = (const float*)d_in[0];
    const float* alpha = (const float*)d_in[1];
    float*       out   = (float*)d_out;

    const int rows = in_sizes[0] / ROW_D;
    entmax_bisect_kernel<<<rows, NTHREADS>>>(x, alpha, out);
}